// round 5
// baseline (speedup 1.0000x reference)
#include <cuda_runtime.h>
#include <cuda_bf16.h>
#include <cstdint>
#include <math.h>

#define B_    16
#define N_    8192
#define C_    256
#define HID_  128
#define KEEP_ 5734
#define M_    (B_*N_)   // 131072 rows
#define BANDCAP 4096
#define MICROCAP 64

// ---------------- scratch (device globals; no allocation allowed) ----------
__device__ float g_scores[M_];
__device__ int   g_idx[B_*KEEP_];
__device__ int   g_band[B_*BANDCAP];
__device__ int   g_bandcnt[B_];
// W1 fragments, mma.m16n8k16 B-operand layout (bf16 RN):
// [kt(16)][nt(16)][lane(32)] uint2 = (b0, b1)
__device__ __align__(16) uint2 g_w1frag[16*16*32];

// ---------------- helpers ---------------------------------------------------
__device__ __forceinline__ uint32_t pack2(__nv_bfloat16 lo, __nv_bfloat16 hi) {
    uint16_t a = __bfloat16_as_ushort(lo);
    uint16_t b = __bfloat16_as_ushort(hi);
    return ((uint32_t)b << 16) | (uint32_t)a;
}

__device__ __forceinline__ uint32_t cvt2(float2 f) {
    __nv_bfloat162 h = __float22bfloat162_rn(f);
    return *(uint32_t*)&h;
}

__device__ __forceinline__ void mma16816(float* c, const uint32_t* a,
                                         uint32_t b0, uint32_t b1) {
    asm volatile(
        "mma.sync.aligned.m16n8k16.row.col.f32.bf16.bf16.f32 "
        "{%0,%1,%2,%3},{%4,%5,%6,%7},{%8,%9},{%0,%1,%2,%3};\n"
        : "+f"(c[0]), "+f"(c[1]), "+f"(c[2]), "+f"(c[3])
        : "r"(a[0]), "r"(a[1]), "r"(a[2]), "r"(a[3]), "r"(b0), "r"(b1));
}

__device__ __forceinline__ float gelu_exact(float x) {
    return 0.5f * x * (1.0f + erff(x * 0.70710678118654752f));
}

__device__ __forceinline__ uint32_t fmap(float f) {
    uint32_t v = __float_as_uint(f);
    return (v & 0x80000000u) ? ~v : (v | 0x80000000u);
}
__device__ __forceinline__ float funmap(uint32_t k) {
    return (k & 0x80000000u) ? __uint_as_float(k ^ 0x80000000u)
                             : __uint_as_float(~k);
}

// ---------------- kernel 1: pack W1 into bf16 mma fragments ----------------
__global__ void prep_w1(const float* __restrict__ W1) {
    int id = blockIdx.x * blockDim.x + threadIdx.x;   // 8192 total
    if (id >= 16*16*32) return;
    int lane = id & 31;
    int kt   = id >> 9;
    int t = lane & 3, g = lane >> 2;
    int nt = (id >> 5) & 15;
    int n  = nt*8 + g;
    int k0 = kt*16 + t*2;
    float w00 = W1[k0*HID_ + n],     w01 = W1[(k0+1)*HID_ + n];
    float w10 = W1[(k0+8)*HID_ + n], w11 = W1[(k0+9)*HID_ + n];
    uint2 v;
    v.x = pack2(__float2bfloat16_rn(w00), __float2bfloat16_rn(w01));
    v.y = pack2(__float2bfloat16_rn(w10), __float2bfloat16_rn(w11));
    g_w1frag[id] = v;
}

// ---------------- kernel 2: screen: fc1(bf16 mma) -> GELU -> fc2 -----------
__global__ void __launch_bounds__(256, 2)
gemm_scores(const float* __restrict__ tokens,
            const float* __restrict__ b1,
            const float* __restrict__ W2) {
    __shared__ float s_b1[HID_], s_w2[HID_];
    const int tid = threadIdx.x;
    if (tid < HID_) { s_b1[tid] = b1[tid]; s_w2[tid] = W2[tid]; }
    __syncthreads();

    const int warp = tid >> 5, lane = tid & 31;
    const int g = lane >> 2, t = lane & 3;
    const long long row0 = (long long)(blockIdx.x * 8 + warp) * 16;
    const float* A0 = tokens + row0 * C_;

    float acc[16][4];
    #pragma unroll
    for (int n = 0; n < 16; n++)
        #pragma unroll
        for (int q = 0; q < 4; q++) acc[n][q] = 0.0f;

    const uint2* Bf = g_w1frag + lane;

    #pragma unroll 4
    for (int kt = 0; kt < 16; kt++) {
        const int col = kt*16 + t*2;
        uint32_t a[4];
        a[0] = cvt2(*(const float2*)(A0 + (g)     * C_ + col));
        a[1] = cvt2(*(const float2*)(A0 + (g + 8) * C_ + col));
        a[2] = cvt2(*(const float2*)(A0 + (g)     * C_ + col + 8));
        a[3] = cvt2(*(const float2*)(A0 + (g + 8) * C_ + col + 8));

        const uint2* bp = Bf + kt*16*32;
        #pragma unroll
        for (int nt = 0; nt < 16; nt++) {
            uint2 bb = bp[nt*32];
            mma16816(acc[nt], a, bb.x, bb.y);
        }
    }

    float p0 = 0.0f, p1 = 0.0f;
    #pragma unroll
    for (int nt = 0; nt < 16; nt++) {
        int c0 = nt*8 + t*2, c1 = c0 + 1;
        p0 += gelu_exact(acc[nt][0] + s_b1[c0]) * s_w2[c0];
        p0 += gelu_exact(acc[nt][1] + s_b1[c1]) * s_w2[c1];
        p1 += gelu_exact(acc[nt][2] + s_b1[c0]) * s_w2[c0];
        p1 += gelu_exact(acc[nt][3] + s_b1[c1]) * s_w2[c1];
    }
    p0 += __shfl_xor_sync(0xffffffffu, p0, 1);
    p0 += __shfl_xor_sync(0xffffffffu, p0, 2);
    p1 += __shfl_xor_sync(0xffffffffu, p1, 1);
    p1 += __shfl_xor_sync(0xffffffffu, p1, 2);
    if (t == 0) {
        g_scores[row0 + g]     = p0;
        g_scores[row0 + 8 + g] = p1;
    }
}

// ---------------- radix select core (device) --------------------------------
struct SelResult { uint32_t T; int need_eq; };

__device__ SelResult radix_select_smem(const uint32_t* keys, int tid,
                                       int* hist, int* sh_Krem,
                                       uint32_t* sh_prefix) {
    if (tid == 0) { *sh_Krem = KEEP_; *sh_prefix = 0u; }
    __syncthreads();
    for (int level = 0; level < 4; level++) {
        int shift = 24 - 8*level;
        if (tid < 256) hist[tid] = 0;
        __syncthreads();
        uint32_t pmask = (level == 0) ? 0u : (0xFFFFFFFFu << (shift + 8));
        uint32_t pref = *sh_prefix;
        for (int i = tid; i < N_; i += 1024) {
            uint32_t v = keys[i];
            if ((v & pmask) == pref) atomicAdd(&hist[(v >> shift) & 255], 1);
        }
        __syncthreads();
        if (tid == 0) {
            int K = *sh_Krem, cum = 0;
            for (int d = 255; d >= 0; d--) {
                int c = hist[d];
                if (cum + c >= K) {
                    *sh_prefix = pref | ((uint32_t)d << shift);
                    *sh_Krem = K - cum;
                    break;
                }
                cum += c;
            }
        }
        __syncthreads();
    }
    SelResult r; r.T = *sh_prefix; r.need_eq = *sh_Krem;
    __syncthreads();
    return r;
}

// ---------------- kernel 3: approx threshold + band collection -------------
__global__ void __launch_bounds__(1024) band_setup() {
    __shared__ uint32_t keys[N_];
    __shared__ int hist[256];
    __shared__ int sh_Krem;
    __shared__ uint32_t sh_prefix;
    __shared__ float s_ss;

    const int b = blockIdx.x, tid = threadIdx.x;
    const int lane = tid & 31;

    if (tid == 0) { s_ss = 0.0f; g_bandcnt[b] = 0; }
    __syncthreads();

    float lss = 0.0f;
    for (int i = tid; i < N_; i += 1024) {
        float s = g_scores[b*N_ + i];
        lss += s * s;
        keys[i] = fmap(s);
    }
    #pragma unroll
    for (int o = 16; o; o >>= 1) lss += __shfl_xor_sync(0xffffffffu, lss, o);
    if (lane == 0) atomicAdd(&s_ss, lss);
    __syncthreads();

    SelResult sel = radix_select_smem(keys, tid, hist, &sh_Krem, &sh_prefix);
    float Tf = funmap(sel.T);
    float delta = 0.04f * sqrtf(s_ss / (float)N_) + 1e-5f;

    for (int i = tid; i < N_; i += 1024) {
        float s = g_scores[b*N_ + i];
        if (fabsf(s - Tf) <= delta) {
            int p = atomicAdd(&g_bandcnt[b], 1);
            if (p < BANDCAP) g_band[b*BANDCAP + p] = i;
        }
    }
}

// ---------------- kernel 4: fp32 Dot2 rescore of band rows (no fp64) -------
// Dot2 (TwoProdFMA + 2Sum) dot, fp32 erff GELU + Kahan epilogue.
// Total abs error <= ~3e-7 << micro-band half width (2e-5).
__global__ void __launch_bounds__(256)
refine_band(const float* __restrict__ tokens, const float* __restrict__ W1,
            const float* __restrict__ b1, const float* __restrict__ W2) {
    __shared__ float sx[8][C_];
    const int b    = blockIdx.y;
    const int warp = threadIdx.x >> 5, lane = threadIdx.x & 31;
    const int cnt = min(g_bandcnt[b], BANDCAP);
    const int nwarps = gridDim.x * 8;
    const int w0 = blockIdx.x * 8 + warp;

    for (int e = w0; e < cnt; e += nwarps) {
        const int r = g_band[b*BANDCAP + e];
        const float4* src = (const float4*)(tokens + ((long long)(b*N_ + r)) * C_);
        ((float4*)sx[warp])[lane]      = src[lane];
        ((float4*)sx[warp])[lane + 32] = src[lane + 32];
        __syncwarp();

        float s[4], cc[4];
        #pragma unroll
        for (int q = 0; q < 4; q++) { s[q] = 0.0f; cc[q] = 0.0f; }

        #pragma unroll 4
        for (int k = 0; k < C_; k++) {
            float4 wv = __ldg((const float4*)(W1 + k*HID_) + lane);
            float wq[4] = {wv.x, wv.y, wv.z, wv.w};
            float xk = sx[warp][k];
            #pragma unroll
            for (int q = 0; q < 4; q++) {
                float p  = xk * wq[q];
                float er = fmaf(xk, wq[q], -p);
                float tn = s[q] + p;
                float z  = tn - s[q];
                float e2 = (s[q] - (tn - z)) + (p - z);
                s[q] = tn;
                cc[q] += er + e2;
            }
        }

        // fp32 epilogue, Kahan-compensated over the 4 local terms
        float sum = 0.0f, comp = 0.0f;
        #pragma unroll
        for (int q = 0; q < 4; q++) {
            int h = lane*4 + q;
            float hv = s[q] + (cc[q] + b1[h]);
            float gl = gelu_exact(hv) * W2[h];
            float y = gl - comp;
            float tnn = sum + y;
            comp = (tnn - sum) - y;
            sum = tnn;
        }
        #pragma unroll
        for (int o = 16; o; o >>= 1)
            sum += __shfl_xor_sync(0xffffffffu, sum, o);
        if (lane == 0) g_scores[b*N_ + r] = sum;
        __syncwarp();
    }
}

// ---------------- kernel 5: final select + in-CTA fp64 micro-resolve -------
__device__ __forceinline__ int block_exscan(int v, int* sw, int tid) {
    int lane = tid & 31, w = tid >> 5;
    int x = v;
    #pragma unroll
    for (int o = 1; o < 32; o <<= 1) {
        int y = __shfl_up_sync(0xffffffffu, x, o);
        if (lane >= o) x += y;
    }
    __syncthreads();
    if (lane == 31) sw[w] = x;
    __syncthreads();
    if (w == 0) {
        int s = sw[lane];
        #pragma unroll
        for (int o = 1; o < 32; o <<= 1) {
            int y = __shfl_up_sync(0xffffffffu, s, o);
            if (lane >= o) s += y;
        }
        sw[lane] = s;
    }
    __syncthreads();
    int base = (w == 0) ? 0 : sw[w-1];
    return base + x - v;
}

__global__ void __launch_bounds__(1024)
select_final(const float* __restrict__ tokens, const float* __restrict__ W1,
             const float* __restrict__ b1, const float* __restrict__ W2) {
    __shared__ uint32_t keys[N_];
    __shared__ int hist[256];
    __shared__ int sw[32];
    __shared__ int sh_Krem;
    __shared__ uint32_t sh_prefix;
    __shared__ int mlist[MICROCAP];
    __shared__ int mcnt;

    const int b = blockIdx.x, tid = threadIdx.x;
    const int warp = tid >> 5, lane = tid & 31;

    if (tid == 0) mcnt = 0;
    for (int i = tid; i < N_; i += 1024)
        keys[i] = fmap(g_scores[b*N_ + i]);
    __syncthreads();

    SelResult sel = radix_select_smem(keys, tid, hist, &sh_Krem, &sh_prefix);
    float Tf = funmap(sel.T);

    // micro-band: rows whose fp32-refined score is within 2e-5 of threshold
    for (int i = tid; i < N_; i += 1024) {
        float s = g_scores[b*N_ + i];
        if (fabsf(s - Tf) <= 2e-5f) {
            int p = atomicAdd(&mcnt, 1);
            if (p < MICROCAP) mlist[p] = i;
        }
    }
    __syncthreads();
    const int mc = min(mcnt, MICROCAP);

    // fp64-grade rescore of micro rows: one row per warp (32 warps)
    for (int e = warp; e < mc; e += 32) {
        const int r = mlist[e];
        const float* X = tokens + ((long long)(b*N_ + r)) * C_;

        float s[4], cc[4];
        #pragma unroll
        for (int q = 0; q < 4; q++) { s[q] = 0.0f; cc[q] = 0.0f; }
        #pragma unroll 4
        for (int k = 0; k < C_; k++) {
            float4 wv = __ldg((const float4*)(W1 + k*HID_) + lane);
            float wq[4] = {wv.x, wv.y, wv.z, wv.w};
            float xk = __ldg(X + k);
            #pragma unroll
            for (int q = 0; q < 4; q++) {
                float p  = xk * wq[q];
                float er = fmaf(xk, wq[q], -p);
                float tn = s[q] + p;
                float z  = tn - s[q];
                float e2 = (s[q] - (tn - z)) + (p - z);
                s[q] = tn;
                cc[q] += er + e2;
            }
        }
        double sd = 0.0;
        #pragma unroll
        for (int q = 0; q < 4; q++) {
            int h = lane*4 + q;
            double hv = (double)s[q] + (double)cc[q] + (double)b1[h];
            double gl = 0.5 * hv * (1.0 + erf(hv * 0.70710678118654752440));
            sd += gl * (double)W2[h];
        }
        #pragma unroll
        for (int o = 16; o; o >>= 1)
            sd += __shfl_xor_sync(0xffffffffu, sd, o);
        if (lane == 0) keys[r] = fmap((float)sd);
    }
    __syncthreads();

    // final exact select on resolved keys
    SelResult sel2 = radix_select_smem(keys, tid, hist, &sh_Krem, &sh_prefix);
    const uint32_t T = sel2.T;
    const int need_eq = sel2.need_eq;

    const int base_i = tid * 8;
    int eqc = 0;
    #pragma unroll
    for (int j = 0; j < 8; j++) eqc += (keys[base_i + j] == T);
    int e = block_exscan(eqc, sw, tid);

    int keepc = 0;
    unsigned char kp[8];
    #pragma unroll
    for (int j = 0; j < 8; j++) {
        uint32_t v = keys[base_i + j];
        bool k = (v > T);
        if (v == T) { k = (e < need_eq); e++; }
        kp[j] = k; keepc += k;
    }
    int pos = block_exscan(keepc, sw, tid);
    #pragma unroll
    for (int j = 0; j < 8; j++) {
        if (kp[j]) { g_idx[b*KEEP_ + pos] = base_i + j; pos++; }
    }
}

// ---------------- kernel 6: gather pruned tokens + emit indices ------------
__global__ void __launch_bounds__(512)
gather_rows(const float* __restrict__ tokens, float* __restrict__ out,
            int write_idx) {
    int rid = blockIdx.x * 16 + (threadIdx.x >> 5);
    if (rid >= B_*KEEP_) return;
    int lane = threadIdx.x & 31;
    int b = rid / KEEP_;
    int idx = g_idx[rid];
    const float4* s = (const float4*)(tokens + ((long long)(b*N_ + idx)) * C_);
    float4* d = (float4*)(out + (long long)rid * C_);
    d[lane]      = s[lane];
    d[lane + 32] = s[lane + 32];
    if (write_idx && lane == 0)
        out[(long long)B_*KEEP_*C_ + rid] = (float)idx;
}

// ---------------- launch ----------------------------------------------------
extern "C" void kernel_launch(void* const* d_in, const int* in_sizes, int n_in,
                              void* d_out, int out_size) {
    const float* tokens = (const float*)d_in[0];
    const float* W1     = (const float*)d_in[1];
    const float* b1     = (const float*)d_in[2];
    const float* W2     = (const float*)d_in[3];
    // b2 shifts all scores equally -> selection-invariant; not in output.

    prep_w1<<<32, 256>>>(W1);

    gemm_scores<<<M_/128, 256>>>(tokens, b1, W2);

    band_setup<<<B_, 1024>>>();

    refine_band<<<dim3(19, B_), 256>>>(tokens, W1, b1, W2);

    select_final<<<B_, 1024>>>(tokens, W1, b1, W2);

    long long prunedN = (long long)B_ * KEEP_ * C_;
    int wi = ((long long)out_size >= prunedN + (long long)B_*KEEP_) ? 1 : 0;
    gather_rows<<<(B_*KEEP_ + 15)/16, 512>>>(tokens, (float*)d_out, wi);
}

// round 6
// speedup vs baseline: 1.1113x; 1.1113x over previous
#include <cuda_runtime.h>
#include <cuda_bf16.h>
#include <cstdint>
#include <math.h>

#define B_    16
#define N_    8192
#define C_    256
#define HID_  128
#define KEEP_ 5734
#define M_    (B_*N_)   // 131072 rows
#define BANDCAP 4096
#define MICROCAP 64

// ---------------- scratch (device globals; no allocation allowed) ----------
__device__ float g_scores[M_];
__device__ int   g_idx[B_*KEEP_];
__device__ int   g_band[B_*BANDCAP];
__device__ int   g_bandcnt[B_];
// W1 fragments, mma.m16n8k16 B-operand layout (bf16 RN):
// [kt(16)][nt(16)][lane(32)] uint2 = (b0, b1)
__device__ __align__(16) uint2 g_w1frag[16*16*32];

// ---------------- helpers ---------------------------------------------------
__device__ __forceinline__ uint32_t pack2(__nv_bfloat16 lo, __nv_bfloat16 hi) {
    uint16_t a = __bfloat16_as_ushort(lo);
    uint16_t b = __bfloat16_as_ushort(hi);
    return ((uint32_t)b << 16) | (uint32_t)a;
}

__device__ __forceinline__ uint32_t cvt2(float2 f) {
    __nv_bfloat162 h = __float22bfloat162_rn(f);
    return *(uint32_t*)&h;
}

__device__ __forceinline__ void mma16816(float* c, const uint32_t* a,
                                         uint32_t b0, uint32_t b1) {
    asm volatile(
        "mma.sync.aligned.m16n8k16.row.col.f32.bf16.bf16.f32 "
        "{%0,%1,%2,%3},{%4,%5,%6,%7},{%8,%9},{%0,%1,%2,%3};\n"
        : "+f"(c[0]), "+f"(c[1]), "+f"(c[2]), "+f"(c[3])
        : "r"(a[0]), "r"(a[1]), "r"(a[2]), "r"(a[3]), "r"(b0), "r"(b1));
}

__device__ __forceinline__ float gelu_exact(float x) {
    return 0.5f * x * (1.0f + erff(x * 0.70710678118654752f));
}

__device__ __forceinline__ uint32_t fmap(float f) {
    uint32_t v = __float_as_uint(f);
    return (v & 0x80000000u) ? ~v : (v | 0x80000000u);
}
__device__ __forceinline__ float funmap(uint32_t k) {
    return (k & 0x80000000u) ? __uint_as_float(k ^ 0x80000000u)
                             : __uint_as_float(~k);
}

// ---------------- kernel 1: pack W1 into bf16 mma fragments ----------------
__global__ void prep_w1(const float* __restrict__ W1) {
    int id = blockIdx.x * blockDim.x + threadIdx.x;   // 8192 total
    if (id >= 16*16*32) return;
    int lane = id & 31;
    int kt   = id >> 9;
    int t = lane & 3, g = lane >> 2;
    int nt = (id >> 5) & 15;
    int n  = nt*8 + g;
    int k0 = kt*16 + t*2;
    float w00 = W1[k0*HID_ + n],     w01 = W1[(k0+1)*HID_ + n];
    float w10 = W1[(k0+8)*HID_ + n], w11 = W1[(k0+9)*HID_ + n];
    uint2 v;
    v.x = pack2(__float2bfloat16_rn(w00), __float2bfloat16_rn(w01));
    v.y = pack2(__float2bfloat16_rn(w10), __float2bfloat16_rn(w11));
    g_w1frag[id] = v;
}

// ---------------- kernel 2: screen: fc1(bf16 mma) -> GELU -> fc2 -----------
__global__ void __launch_bounds__(256, 2)
gemm_scores(const float* __restrict__ tokens,
            const float* __restrict__ b1,
            const float* __restrict__ W2) {
    __shared__ float s_b1[HID_], s_w2[HID_];
    const int tid = threadIdx.x;
    if (tid < HID_) { s_b1[tid] = b1[tid]; s_w2[tid] = W2[tid]; }
    __syncthreads();

    const int warp = tid >> 5, lane = tid & 31;
    const int g = lane >> 2, t = lane & 3;
    const long long row0 = (long long)(blockIdx.x * 8 + warp) * 16;
    const float* A0 = tokens + row0 * C_;

    float acc[16][4];
    #pragma unroll
    for (int n = 0; n < 16; n++)
        #pragma unroll
        for (int q = 0; q < 4; q++) acc[n][q] = 0.0f;

    const uint2* Bf = g_w1frag + lane;

    #pragma unroll 4
    for (int kt = 0; kt < 16; kt++) {
        const int col = kt*16 + t*2;
        uint32_t a[4];
        a[0] = cvt2(*(const float2*)(A0 + (g)     * C_ + col));
        a[1] = cvt2(*(const float2*)(A0 + (g + 8) * C_ + col));
        a[2] = cvt2(*(const float2*)(A0 + (g)     * C_ + col + 8));
        a[3] = cvt2(*(const float2*)(A0 + (g + 8) * C_ + col + 8));

        const uint2* bp = Bf + kt*16*32;
        #pragma unroll
        for (int nt = 0; nt < 16; nt++) {
            uint2 bb = bp[nt*32];
            mma16816(acc[nt], a, bb.x, bb.y);
        }
    }

    float p0 = 0.0f, p1 = 0.0f;
    #pragma unroll
    for (int nt = 0; nt < 16; nt++) {
        int c0 = nt*8 + t*2, c1 = c0 + 1;
        p0 += gelu_exact(acc[nt][0] + s_b1[c0]) * s_w2[c0];
        p0 += gelu_exact(acc[nt][1] + s_b1[c1]) * s_w2[c1];
        p1 += gelu_exact(acc[nt][2] + s_b1[c0]) * s_w2[c0];
        p1 += gelu_exact(acc[nt][3] + s_b1[c1]) * s_w2[c1];
    }
    p0 += __shfl_xor_sync(0xffffffffu, p0, 1);
    p0 += __shfl_xor_sync(0xffffffffu, p0, 2);
    p1 += __shfl_xor_sync(0xffffffffu, p1, 1);
    p1 += __shfl_xor_sync(0xffffffffu, p1, 2);
    if (t == 0) {
        g_scores[row0 + g]     = p0;
        g_scores[row0 + 8 + g] = p1;
    }
}

// ---------------- radix select core (device) --------------------------------
struct SelResult { uint32_t T; int need_eq; };

__device__ SelResult radix_select_smem(const uint32_t* keys, int tid,
                                       int* hist, int* sh_Krem,
                                       uint32_t* sh_prefix) {
    if (tid == 0) { *sh_Krem = KEEP_; *sh_prefix = 0u; }
    __syncthreads();
    for (int level = 0; level < 4; level++) {
        int shift = 24 - 8*level;
        if (tid < 256) hist[tid] = 0;
        __syncthreads();
        uint32_t pmask = (level == 0) ? 0u : (0xFFFFFFFFu << (shift + 8));
        uint32_t pref = *sh_prefix;
        for (int i = tid; i < N_; i += 1024) {
            uint32_t v = keys[i];
            if ((v & pmask) == pref) atomicAdd(&hist[(v >> shift) & 255], 1);
        }
        __syncthreads();
        if (tid == 0) {
            int K = *sh_Krem, cum = 0;
            for (int d = 255; d >= 0; d--) {
                int c = hist[d];
                if (cum + c >= K) {
                    *sh_prefix = pref | ((uint32_t)d << shift);
                    *sh_Krem = K - cum;
                    break;
                }
                cum += c;
            }
        }
        __syncthreads();
    }
    SelResult r; r.T = *sh_prefix; r.need_eq = *sh_Krem;
    __syncthreads();
    return r;
}

// ---------------- kernel 3: approx threshold + band collection -------------
__global__ void __launch_bounds__(1024) band_setup() {
    __shared__ uint32_t keys[N_];
    __shared__ int hist[256];
    __shared__ int sh_Krem;
    __shared__ uint32_t sh_prefix;
    __shared__ float s_ss;

    const int b = blockIdx.x, tid = threadIdx.x;
    const int lane = tid & 31;

    if (tid == 0) { s_ss = 0.0f; g_bandcnt[b] = 0; }
    __syncthreads();

    float lss = 0.0f;
    for (int i = tid; i < N_; i += 1024) {
        float s = g_scores[b*N_ + i];
        lss += s * s;
        keys[i] = fmap(s);
    }
    #pragma unroll
    for (int o = 16; o; o >>= 1) lss += __shfl_xor_sync(0xffffffffu, lss, o);
    if (lane == 0) atomicAdd(&s_ss, lss);
    __syncthreads();

    SelResult sel = radix_select_smem(keys, tid, hist, &sh_Krem, &sh_prefix);
    float Tf = funmap(sel.T);
    float delta = 0.04f * sqrtf(s_ss / (float)N_) + 1e-5f;

    for (int i = tid; i < N_; i += 1024) {
        float s = g_scores[b*N_ + i];
        if (fabsf(s - Tf) <= delta) {
            int p = atomicAdd(&g_bandcnt[b], 1);
            if (p < BANDCAP) g_band[b*BANDCAP + p] = i;
        }
    }
}

// ---------------- kernel 4: fp32 rescore of band rows (plain FMA) ----------
// 4 rows per warp share each W1 read. Plain fp32 dot: abs err <~1e-5, which
// is covered by the 5e-5 micro-band + fp64 resolve in select_final.
__global__ void __launch_bounds__(256)
refine_band(const float* __restrict__ tokens, const float* __restrict__ W1,
            const float* __restrict__ b1, const float* __restrict__ W2) {
    __shared__ float sx[8][4][C_];   // 8 warps x 4 rows x 256 = 32KB
    const int b    = blockIdx.y;
    const int warp = threadIdx.x >> 5, lane = threadIdx.x & 31;
    const int cnt = min(g_bandcnt[b], BANDCAP);
    const int nwarps = gridDim.x * 8;
    const int w0 = blockIdx.x * 8 + warp;

    for (int base = w0*4; base < cnt; base += nwarps*4) {
        const int nrows = min(4, cnt - base);
        for (int j = 0; j < nrows; j++) {
            int r = g_band[b*BANDCAP + base + j];
            const float4* src = (const float4*)(tokens + ((long long)(b*N_ + r)) * C_);
            ((float4*)sx[warp][j])[lane]      = src[lane];
            ((float4*)sx[warp][j])[lane + 32] = src[lane + 32];
        }
        __syncwarp();

        float acc[4][4];
        #pragma unroll
        for (int j = 0; j < 4; j++)
            #pragma unroll
            for (int q = 0; q < 4; q++) acc[j][q] = 0.0f;

        #pragma unroll 4
        for (int k = 0; k < C_; k++) {
            float4 wv = __ldg((const float4*)(W1 + k*HID_) + lane);
            #pragma unroll
            for (int j = 0; j < 4; j++) {
                float xk = sx[warp][j][k];
                acc[j][0] = fmaf(xk, wv.x, acc[j][0]);
                acc[j][1] = fmaf(xk, wv.y, acc[j][1]);
                acc[j][2] = fmaf(xk, wv.z, acc[j][2]);
                acc[j][3] = fmaf(xk, wv.w, acc[j][3]);
            }
        }

        for (int j = 0; j < nrows; j++) {
            float sum = 0.0f;
            #pragma unroll
            for (int q = 0; q < 4; q++) {
                int h = lane*4 + q;
                sum += gelu_exact(acc[j][q] + b1[h]) * W2[h];
            }
            #pragma unroll
            for (int o = 16; o; o >>= 1)
                sum += __shfl_xor_sync(0xffffffffu, sum, o);
            if (lane == 0) {
                int r = g_band[b*BANDCAP + base + j];
                g_scores[b*N_ + r] = sum;
            }
        }
        __syncwarp();
    }
}

// ---------------- kernel 5: final select + in-CTA fp64 micro-resolve -------
__device__ __forceinline__ int block_exscan(int v, int* sw, int tid) {
    int lane = tid & 31, w = tid >> 5;
    int x = v;
    #pragma unroll
    for (int o = 1; o < 32; o <<= 1) {
        int y = __shfl_up_sync(0xffffffffu, x, o);
        if (lane >= o) x += y;
    }
    __syncthreads();
    if (lane == 31) sw[w] = x;
    __syncthreads();
    if (w == 0) {
        int s = sw[lane];
        #pragma unroll
        for (int o = 1; o < 32; o <<= 1) {
            int y = __shfl_up_sync(0xffffffffu, s, o);
            if (lane >= o) s += y;
        }
        sw[lane] = s;
    }
    __syncthreads();
    int base = (w == 0) ? 0 : sw[w-1];
    return base + x - v;
}

__global__ void __launch_bounds__(1024)
select_final(const float* __restrict__ tokens, const float* __restrict__ W1,
             const float* __restrict__ b1, const float* __restrict__ W2) {
    __shared__ uint32_t keys[N_];
    __shared__ int hist[256];
    __shared__ int sw[32];
    __shared__ int sh_Krem;
    __shared__ uint32_t sh_prefix;
    __shared__ int mlist[MICROCAP];
    __shared__ int mcnt;

    const int b = blockIdx.x, tid = threadIdx.x;
    const int warp = tid >> 5, lane = tid & 31;

    if (tid == 0) mcnt = 0;
    for (int i = tid; i < N_; i += 1024)
        keys[i] = fmap(g_scores[b*N_ + i]);
    __syncthreads();

    SelResult sel = radix_select_smem(keys, tid, hist, &sh_Krem, &sh_prefix);
    float Tf = funmap(sel.T);

    // micro-band: rows whose fp32-refined score is within 5e-5 of threshold
    for (int i = tid; i < N_; i += 1024) {
        float s = g_scores[b*N_ + i];
        if (fabsf(s - Tf) <= 5e-5f) {
            int p = atomicAdd(&mcnt, 1);
            if (p < MICROCAP) mlist[p] = i;
        }
    }
    __syncthreads();
    const int mc = min(mcnt, MICROCAP);

    // fp64-grade rescore of micro rows: one row per warp (32 warps)
    for (int e = warp; e < mc; e += 32) {
        const int r = mlist[e];
        const float* X = tokens + ((long long)(b*N_ + r)) * C_;

        float s[4], cc[4];
        #pragma unroll
        for (int q = 0; q < 4; q++) { s[q] = 0.0f; cc[q] = 0.0f; }
        #pragma unroll 4
        for (int k = 0; k < C_; k++) {
            float4 wv = __ldg((const float4*)(W1 + k*HID_) + lane);
            float wq[4] = {wv.x, wv.y, wv.z, wv.w};
            float xk = __ldg(X + k);
            #pragma unroll
            for (int q = 0; q < 4; q++) {
                float p  = xk * wq[q];
                float er = fmaf(xk, wq[q], -p);
                float tn = s[q] + p;
                float z  = tn - s[q];
                float e2 = (s[q] - (tn - z)) + (p - z);
                s[q] = tn;
                cc[q] += er + e2;
            }
        }
        double sd = 0.0;
        #pragma unroll
        for (int q = 0; q < 4; q++) {
            int h = lane*4 + q;
            double hv = (double)s[q] + (double)cc[q] + (double)b1[h];
            double gl = 0.5 * hv * (1.0 + erf(hv * 0.70710678118654752440));
            sd += gl * (double)W2[h];
        }
        #pragma unroll
        for (int o = 16; o; o >>= 1)
            sd += __shfl_xor_sync(0xffffffffu, sd, o);
        if (lane == 0) keys[r] = fmap((float)sd);
    }
    __syncthreads();

    // final exact select on resolved keys
    SelResult sel2 = radix_select_smem(keys, tid, hist, &sh_Krem, &sh_prefix);
    const uint32_t T = sel2.T;
    const int need_eq = sel2.need_eq;

    const int base_i = tid * 8;
    int eqc = 0;
    #pragma unroll
    for (int j = 0; j < 8; j++) eqc += (keys[base_i + j] == T);
    int e = block_exscan(eqc, sw, tid);

    int keepc = 0;
    unsigned char kp[8];
    #pragma unroll
    for (int j = 0; j < 8; j++) {
        uint32_t v = keys[base_i + j];
        bool k = (v > T);
        if (v == T) { k = (e < need_eq); e++; }
        kp[j] = k; keepc += k;
    }
    int pos = block_exscan(keepc, sw, tid);
    #pragma unroll
    for (int j = 0; j < 8; j++) {
        if (kp[j]) { g_idx[b*KEEP_ + pos] = base_i + j; pos++; }
    }
}

// ---------------- kernel 6: gather pruned tokens + emit indices ------------
__global__ void __launch_bounds__(512)
gather_rows(const float* __restrict__ tokens, float* __restrict__ out,
            int write_idx) {
    int rid = blockIdx.x * 16 + (threadIdx.x >> 5);
    if (rid >= B_*KEEP_) return;
    int lane = threadIdx.x & 31;
    int b = rid / KEEP_;
    int idx = g_idx[rid];
    const float4* s = (const float4*)(tokens + ((long long)(b*N_ + idx)) * C_);
    float4* d = (float4*)(out + (long long)rid * C_);
    d[lane]      = s[lane];
    d[lane + 32] = s[lane + 32];
    if (write_idx && lane == 0)
        out[(long long)B_*KEEP_*C_ + rid] = (float)idx;
}

// ---------------- launch ----------------------------------------------------
extern "C" void kernel_launch(void* const* d_in, const int* in_sizes, int n_in,
                              void* d_out, int out_size) {
    const float* tokens = (const float*)d_in[0];
    const float* W1     = (const float*)d_in[1];
    const float* b1     = (const float*)d_in[2];
    const float* W2     = (const float*)d_in[3];
    // b2 shifts all scores equally -> selection-invariant; not in output.

    prep_w1<<<32, 256>>>(W1);

    gemm_scores<<<M_/128, 256>>>(tokens, b1, W2);

    band_setup<<<B_, 1024>>>();

    refine_band<<<dim3(19, B_), 256>>>(tokens, W1, b1, W2);

    select_final<<<B_, 1024>>>(tokens, W1, b1, W2);

    long long prunedN = (long long)B_ * KEEP_ * C_;
    int wi = ((long long)out_size >= prunedN + (long long)B_*KEEP_) ? 1 : 0;
    gather_rows<<<(B_*KEEP_ + 15)/16, 512>>>(tokens, (float*)d_out, wi);
}

// round 7
// speedup vs baseline: 1.1262x; 1.0134x over previous
#include <cuda_runtime.h>
#include <cuda_bf16.h>
#include <cstdint>
#include <math.h>

#define B_    16
#define N_    8192
#define C_    256
#define HID_  128
#define KEEP_ 5734
#define M_    (B_*N_)   // 131072 rows
#define BANDCAP 4096
#define MICROCAP 64

// ---------------- scratch (device globals; no allocation allowed) ----------
__device__ float g_scores[M_];
__device__ int   g_idx[B_*KEEP_];
__device__ int   g_band[B_*BANDCAP];
__device__ int   g_bandcnt[B_];
// W1 fragments, mma.m16n8k16 B-operand layout:
// hi-only (screen): [kt][nt][lane] uint2 ; hi+lo (refine): uint4
__device__ __align__(16) uint2 g_w1fragH[16*16*32];
__device__ __align__(16) uint4 g_w1frag4[16*16*32];

// ---------------- helpers ---------------------------------------------------
__device__ __forceinline__ uint32_t pack2(__nv_bfloat16 lo, __nv_bfloat16 hi) {
    uint16_t a = __bfloat16_as_ushort(lo);
    uint16_t b = __bfloat16_as_ushort(hi);
    return ((uint32_t)b << 16) | (uint32_t)a;
}

__device__ __forceinline__ uint32_t cvt2(float2 f) {
    __nv_bfloat162 h = __float22bfloat162_rn(f);
    return *(uint32_t*)&h;
}

// split a float2 into bf16 hi pair (returned) and lo pair (out param)
__device__ __forceinline__ uint32_t split2(float2 f, uint32_t& lo) {
    __nv_bfloat16 hx = __float2bfloat16_rn(f.x);
    __nv_bfloat16 hy = __float2bfloat16_rn(f.y);
    lo = pack2(__float2bfloat16_rn(f.x - __bfloat162float(hx)),
               __float2bfloat16_rn(f.y - __bfloat162float(hy)));
    return pack2(hx, hy);
}

__device__ __forceinline__ void mma16816(float* c, const uint32_t* a,
                                         uint32_t b0, uint32_t b1) {
    asm volatile(
        "mma.sync.aligned.m16n8k16.row.col.f32.bf16.bf16.f32 "
        "{%0,%1,%2,%3},{%4,%5,%6,%7},{%8,%9},{%0,%1,%2,%3};\n"
        : "+f"(c[0]), "+f"(c[1]), "+f"(c[2]), "+f"(c[3])
        : "r"(a[0]), "r"(a[1]), "r"(a[2]), "r"(a[3]), "r"(b0), "r"(b1));
}

__device__ __forceinline__ float gelu_exact(float x) {
    return 0.5f * x * (1.0f + erff(x * 0.70710678118654752f));
}

__device__ __forceinline__ uint32_t fmap(float f) {
    uint32_t v = __float_as_uint(f);
    return (v & 0x80000000u) ? ~v : (v | 0x80000000u);
}
__device__ __forceinline__ float funmap(uint32_t k) {
    return (k & 0x80000000u) ? __uint_as_float(k ^ 0x80000000u)
                             : __uint_as_float(~k);
}

// ---------------- kernel 1: pack W1 into bf16 mma fragments ----------------
__global__ void prep_w1(const float* __restrict__ W1) {
    int id = blockIdx.x * blockDim.x + threadIdx.x;   // 8192 total
    if (id >= 16*16*32) return;
    int lane = id & 31;
    int kt   = id >> 9;
    int t = lane & 3, g = lane >> 2;
    int nt = (id >> 5) & 15;
    int n  = nt*8 + g;
    int k0 = kt*16 + t*2;
    float w00 = W1[k0*HID_ + n],     w01 = W1[(k0+1)*HID_ + n];
    float w10 = W1[(k0+8)*HID_ + n], w11 = W1[(k0+9)*HID_ + n];
    __nv_bfloat16 h00 = __float2bfloat16_rn(w00), h01 = __float2bfloat16_rn(w01);
    __nv_bfloat16 h10 = __float2bfloat16_rn(w10), h11 = __float2bfloat16_rn(w11);
    uint4 v;
    v.x = pack2(h00, h01);
    v.y = pack2(h10, h11);
    v.z = pack2(__float2bfloat16_rn(w00 - __bfloat162float(h00)),
                __float2bfloat16_rn(w01 - __bfloat162float(h01)));
    v.w = pack2(__float2bfloat16_rn(w10 - __bfloat162float(h10)),
                __float2bfloat16_rn(w11 - __bfloat162float(h11)));
    g_w1frag4[id] = v;
    g_w1fragH[id] = make_uint2(v.x, v.y);
}

// ---------------- kernel 2: screen: fc1(bf16 mma) -> GELU -> fc2 -----------
__global__ void __launch_bounds__(256, 2)
gemm_scores(const float* __restrict__ tokens,
            const float* __restrict__ b1,
            const float* __restrict__ W2) {
    __shared__ float s_b1[HID_], s_w2[HID_];
    const int tid = threadIdx.x;
    if (tid < HID_) { s_b1[tid] = b1[tid]; s_w2[tid] = W2[tid]; }
    __syncthreads();

    const int warp = tid >> 5, lane = tid & 31;
    const int g = lane >> 2, t = lane & 3;
    const long long row0 = (long long)(blockIdx.x * 8 + warp) * 16;
    const float* A0 = tokens + row0 * C_;

    float acc[16][4];
    #pragma unroll
    for (int n = 0; n < 16; n++)
        #pragma unroll
        for (int q = 0; q < 4; q++) acc[n][q] = 0.0f;

    const uint2* Bf = g_w1fragH + lane;

    #pragma unroll 4
    for (int kt = 0; kt < 16; kt++) {
        const int col = kt*16 + t*2;
        uint32_t a[4];
        a[0] = cvt2(*(const float2*)(A0 + (g)     * C_ + col));
        a[1] = cvt2(*(const float2*)(A0 + (g + 8) * C_ + col));
        a[2] = cvt2(*(const float2*)(A0 + (g)     * C_ + col + 8));
        a[3] = cvt2(*(const float2*)(A0 + (g + 8) * C_ + col + 8));

        const uint2* bp = Bf + kt*16*32;
        #pragma unroll
        for (int nt = 0; nt < 16; nt++) {
            uint2 bb = bp[nt*32];
            mma16816(acc[nt], a, bb.x, bb.y);
        }
    }

    float p0 = 0.0f, p1 = 0.0f;
    #pragma unroll
    for (int nt = 0; nt < 16; nt++) {
        int c0 = nt*8 + t*2, c1 = c0 + 1;
        p0 += gelu_exact(acc[nt][0] + s_b1[c0]) * s_w2[c0];
        p0 += gelu_exact(acc[nt][1] + s_b1[c1]) * s_w2[c1];
        p1 += gelu_exact(acc[nt][2] + s_b1[c0]) * s_w2[c0];
        p1 += gelu_exact(acc[nt][3] + s_b1[c1]) * s_w2[c1];
    }
    p0 += __shfl_xor_sync(0xffffffffu, p0, 1);
    p0 += __shfl_xor_sync(0xffffffffu, p0, 2);
    p1 += __shfl_xor_sync(0xffffffffu, p1, 1);
    p1 += __shfl_xor_sync(0xffffffffu, p1, 2);
    if (t == 0) {
        g_scores[row0 + g]     = p0;
        g_scores[row0 + 8 + g] = p1;
    }
}

// ---------------- radix select core (parallel suffix-scan version) ----------
struct SelResult { uint32_t T; int need_eq; };

__device__ SelResult radix_select_smem(const uint32_t* keys, int tid,
                                       int* hist, int* suf, int* sh_Krem,
                                       uint32_t* sh_prefix) {
    if (tid == 0) { *sh_Krem = KEEP_; *sh_prefix = 0u; }
    __syncthreads();
    for (int level = 0; level < 4; level++) {
        const int shift = 24 - 8*level;
        const int K = *sh_Krem;
        const uint32_t pref = *sh_prefix;
        const uint32_t pmask = (level == 0) ? 0u : (0xFFFFFFFFu << (shift + 8));
        if (tid < 256) hist[tid] = 0;
        __syncthreads();
        for (int i = tid; i < N_; i += 1024) {
            uint32_t v = keys[i];
            if ((v & pmask) == pref) atomicAdd(&hist[(v >> shift) & 255], 1);
        }
        __syncthreads();
        if (tid < 256) suf[tid] = hist[tid];
        __syncthreads();
        #pragma unroll
        for (int st = 1; st < 256; st <<= 1) {
            int v = 0;
            if (tid < 256) v = suf[tid] + ((tid + st < 256) ? suf[tid + st] : 0);
            __syncthreads();
            if (tid < 256) suf[tid] = v;
            __syncthreads();
        }
        if (tid < 256) {
            int incl = suf[tid];
            int above = incl - hist[tid];
            if (incl >= K && above < K) {      // exactly one digit satisfies
                *sh_prefix = pref | ((uint32_t)tid << shift);
                *sh_Krem = K - above;
            }
        }
        __syncthreads();
    }
    SelResult r; r.T = *sh_prefix; r.need_eq = *sh_Krem;
    __syncthreads();
    return r;
}

// ---------------- kernel 3: approx threshold + band collection -------------
__global__ void __launch_bounds__(1024) band_setup() {
    __shared__ uint32_t keys[N_];
    __shared__ int hist[256], suf[256];
    __shared__ int sh_Krem;
    __shared__ uint32_t sh_prefix;
    __shared__ float s_ss;

    const int b = blockIdx.x, tid = threadIdx.x;
    const int lane = tid & 31;

    if (tid == 0) { s_ss = 0.0f; g_bandcnt[b] = 0; }
    __syncthreads();

    float lss = 0.0f;
    for (int i = tid; i < N_; i += 1024) {
        float s = g_scores[b*N_ + i];
        lss += s * s;
        keys[i] = fmap(s);
    }
    #pragma unroll
    for (int o = 16; o; o >>= 1) lss += __shfl_xor_sync(0xffffffffu, lss, o);
    if (lane == 0) atomicAdd(&s_ss, lss);
    __syncthreads();

    SelResult sel = radix_select_smem(keys, tid, hist, suf, &sh_Krem, &sh_prefix);
    float Tf = funmap(sel.T);
    float delta = 0.04f * sqrtf(s_ss / (float)N_) + 1e-5f;

    for (int i = tid; i < N_; i += 1024) {
        float s = g_scores[b*N_ + i];
        if (fabsf(s - Tf) <= delta) {
            int p = atomicAdd(&g_bandcnt[b], 1);
            if (p < BANDCAP) g_band[b*BANDCAP + p] = i;
        }
    }
}

// ---------------- kernel 4: split-bf16 mma rescore of band rows ------------
// 3-pass split (hi*hi + hi*lo + lo*hi): score err ~1e-5 << micro-band 3e-4.
// Each warp processes a 16-row tile of band rows (row-indirect A loads).
__global__ void __launch_bounds__(256)
refine_mma(const float* __restrict__ tokens,
           const float* __restrict__ b1, const float* __restrict__ W2) {
    __shared__ float s_b1[HID_], s_w2[HID_];
    const int tid = threadIdx.x;
    if (tid < HID_) { s_b1[tid] = b1[tid]; s_w2[tid] = W2[tid]; }
    __syncthreads();

    const int b = blockIdx.y;
    const int warp = tid >> 5, lane = tid & 31;
    const int g = lane >> 2, t = lane & 3;
    const int cnt = min(g_bandcnt[b], BANDCAP);
    const int nwarps = gridDim.x * 8;
    const int wg = blockIdx.x * 8 + warp;

    const uint4* Bf = g_w1frag4 + lane;

    for (int base = wg*16; base < cnt; base += nwarps*16) {
        const int nrows = cnt - base;   // >=1
        const int e0 = base + ((g     < nrows) ? g     : 0);
        const int e1 = base + ((g + 8 < nrows) ? g + 8 : 0);
        const int r0 = g_band[b*BANDCAP + e0];
        const int r1 = g_band[b*BANDCAP + e1];
        const float* A0 = tokens + ((long long)(b*N_ + r0)) * C_;
        const float* A1 = tokens + ((long long)(b*N_ + r1)) * C_;

        float acc[16][4];
        #pragma unroll
        for (int n = 0; n < 16; n++)
            #pragma unroll
            for (int q = 0; q < 4; q++) acc[n][q] = 0.0f;

        #pragma unroll 4
        for (int kt = 0; kt < 16; kt++) {
            const int col = kt*16 + t*2;
            uint32_t aH[4], aL[4];
            aH[0] = split2(*(const float2*)(A0 + col),     aL[0]);
            aH[1] = split2(*(const float2*)(A1 + col),     aL[1]);
            aH[2] = split2(*(const float2*)(A0 + col + 8), aL[2]);
            aH[3] = split2(*(const float2*)(A1 + col + 8), aL[3]);

            const uint4* bp = Bf + kt*16*32;
            #pragma unroll
            for (int nt = 0; nt < 16; nt++) {
                uint4 bb = bp[nt*32];
                mma16816(acc[nt], aH, bb.x, bb.y);
                mma16816(acc[nt], aH, bb.z, bb.w);
                mma16816(acc[nt], aL, bb.x, bb.y);
            }
        }

        float p0 = 0.0f, p1 = 0.0f;
        #pragma unroll
        for (int nt = 0; nt < 16; nt++) {
            int c0 = nt*8 + t*2, c1 = c0 + 1;
            p0 += gelu_exact(acc[nt][0] + s_b1[c0]) * s_w2[c0];
            p0 += gelu_exact(acc[nt][1] + s_b1[c1]) * s_w2[c1];
            p1 += gelu_exact(acc[nt][2] + s_b1[c0]) * s_w2[c0];
            p1 += gelu_exact(acc[nt][3] + s_b1[c1]) * s_w2[c1];
        }
        p0 += __shfl_xor_sync(0xffffffffu, p0, 1);
        p0 += __shfl_xor_sync(0xffffffffu, p0, 2);
        p1 += __shfl_xor_sync(0xffffffffu, p1, 1);
        p1 += __shfl_xor_sync(0xffffffffu, p1, 2);
        if (t == 0) {
            if (g < nrows)     g_scores[b*N_ + r0] = p0;
            if (g + 8 < nrows) g_scores[b*N_ + r1] = p1;
        }
    }
}

// ---------------- kernel 5: final select + in-CTA fp64 micro-resolve -------
__device__ __forceinline__ int block_exscan(int v, int* sw, int tid) {
    int lane = tid & 31, w = tid >> 5;
    int x = v;
    #pragma unroll
    for (int o = 1; o < 32; o <<= 1) {
        int y = __shfl_up_sync(0xffffffffu, x, o);
        if (lane >= o) x += y;
    }
    __syncthreads();
    if (lane == 31) sw[w] = x;
    __syncthreads();
    if (w == 0) {
        int s = sw[lane];
        #pragma unroll
        for (int o = 1; o < 32; o <<= 1) {
            int y = __shfl_up_sync(0xffffffffu, s, o);
            if (lane >= o) s += y;
        }
        sw[lane] = s;
    }
    __syncthreads();
    int base = (w == 0) ? 0 : sw[w-1];
    return base + x - v;
}

__global__ void __launch_bounds__(1024)
select_final(const float* __restrict__ tokens, const float* __restrict__ W1,
             const float* __restrict__ b1, const float* __restrict__ W2) {
    __shared__ uint32_t keys[N_];
    __shared__ int hist[256], suf[256];
    __shared__ int sw[32];
    __shared__ int sh_Krem;
    __shared__ uint32_t sh_prefix;
    __shared__ int mlist[MICROCAP];
    __shared__ int mcnt;

    const int b = blockIdx.x, tid = threadIdx.x;
    const int warp = tid >> 5, lane = tid & 31;

    if (tid == 0) mcnt = 0;
    for (int i = tid; i < N_; i += 1024)
        keys[i] = fmap(g_scores[b*N_ + i]);
    __syncthreads();

    SelResult sel = radix_select_smem(keys, tid, hist, suf, &sh_Krem, &sh_prefix);
    float Tf = funmap(sel.T);

    // micro-band: rows within 3e-4 of threshold (refine err ~1e-5 -> 25x)
    for (int i = tid; i < N_; i += 1024) {
        float s = g_scores[b*N_ + i];
        if (fabsf(s - Tf) <= 3e-4f) {
            int p = atomicAdd(&mcnt, 1);
            if (p < MICROCAP) mlist[p] = i;
        }
    }
    __syncthreads();
    const int mc = min(mcnt, MICROCAP);

    // fp64-grade rescore of micro rows: one row per warp (32 warps)
    for (int e = warp; e < mc; e += 32) {
        const int r = mlist[e];
        const float* X = tokens + ((long long)(b*N_ + r)) * C_;

        float s[4], cc[4];
        #pragma unroll
        for (int q = 0; q < 4; q++) { s[q] = 0.0f; cc[q] = 0.0f; }
        #pragma unroll 4
        for (int k = 0; k < C_; k++) {
            float4 wv = __ldg((const float4*)(W1 + k*HID_) + lane);
            float wq[4] = {wv.x, wv.y, wv.z, wv.w};
            float xk = __ldg(X + k);
            #pragma unroll
            for (int q = 0; q < 4; q++) {
                float p  = xk * wq[q];
                float er = fmaf(xk, wq[q], -p);
                float tn = s[q] + p;
                float z  = tn - s[q];
                float e2 = (s[q] - (tn - z)) + (p - z);
                s[q] = tn;
                cc[q] += er + e2;
            }
        }
        double sd = 0.0;
        #pragma unroll
        for (int q = 0; q < 4; q++) {
            int h = lane*4 + q;
            double hv = (double)s[q] + (double)cc[q] + (double)b1[h];
            double gl = 0.5 * hv * (1.0 + erf(hv * 0.70710678118654752440));
            sd += gl * (double)W2[h];
        }
        #pragma unroll
        for (int o = 16; o; o >>= 1)
            sd += __shfl_xor_sync(0xffffffffu, sd, o);
        if (lane == 0) keys[r] = fmap((float)sd);
    }
    __syncthreads();

    // final exact select on resolved keys
    SelResult sel2 = radix_select_smem(keys, tid, hist, suf, &sh_Krem, &sh_prefix);
    const uint32_t T = sel2.T;
    const int need_eq = sel2.need_eq;

    const int base_i = tid * 8;
    int eqc = 0;
    #pragma unroll
    for (int j = 0; j < 8; j++) eqc += (keys[base_i + j] == T);
    int e = block_exscan(eqc, sw, tid);

    int keepc = 0;
    unsigned char kp[8];
    #pragma unroll
    for (int j = 0; j < 8; j++) {
        uint32_t v = keys[base_i + j];
        bool k = (v > T);
        if (v == T) { k = (e < need_eq); e++; }
        kp[j] = k; keepc += k;
    }
    int pos = block_exscan(keepc, sw, tid);
    #pragma unroll
    for (int j = 0; j < 8; j++) {
        if (kp[j]) { g_idx[b*KEEP_ + pos] = base_i + j; pos++; }
    }
}

// ---------------- kernel 6: gather pruned tokens + emit indices ------------
__global__ void __launch_bounds__(512)
gather_rows(const float* __restrict__ tokens, float* __restrict__ out,
            int write_idx) {
    int rid = blockIdx.x * 16 + (threadIdx.x >> 5);
    if (rid >= B_*KEEP_) return;
    int lane = threadIdx.x & 31;
    int b = rid / KEEP_;
    int idx = g_idx[rid];
    const float4* s = (const float4*)(tokens + ((long long)(b*N_ + idx)) * C_);
    float4* d = (float4*)(out + (long long)rid * C_);
    d[lane]      = s[lane];
    d[lane + 32] = s[lane + 32];
    if (write_idx && lane == 0)
        out[(long long)B_*KEEP_*C_ + rid] = (float)idx;
}

// ---------------- launch ----------------------------------------------------
extern "C" void kernel_launch(void* const* d_in, const int* in_sizes, int n_in,
                              void* d_out, int out_size) {
    const float* tokens = (const float*)d_in[0];
    const float* W1     = (const float*)d_in[1];
    const float* b1     = (const float*)d_in[2];
    const float* W2     = (const float*)d_in[3];
    // b2 shifts all scores equally -> selection-invariant; not in output.

    prep_w1<<<32, 256>>>(W1);

    gemm_scores<<<M_/128, 256>>>(tokens, b1, W2);

    band_setup<<<B_, 1024>>>();

    refine_mma<<<dim3(2, B_), 256>>>(tokens, b1, W2);

    select_final<<<B_, 1024>>>(tokens, W1, b1, W2);

    long long prunedN = (long long)B_ * KEEP_ * C_;
    int wi = ((long long)out_size >= prunedN + (long long)B_*KEEP_) ? 1 : 0;
    gather_rows<<<(B_*KEEP_ + 15)/16, 512>>>(tokens, (float*)d_out, wi);
}